// round 2
// baseline (speedup 1.0000x reference)
#include <cuda_runtime.h>
#include <math.h>
#include <stddef.h>

#define NUM_GRAPHS 128
#define NODES_PER_GRAPH 512
#define NUM_NODES (NUM_GRAPHS*NODES_PER_GRAPH)   // 65536
#define NUM_EDGES (NUM_NODES*16)                 // 1048576
#define IN_DIM 64
#define HID 128
#define QKV_DIM 384
#define BN_EPS 1e-5f

// ------------------------ scratch (device globals: no allocation) ------------------------
__device__ float g_gbuf[NUM_NODES*HID];          // dis-scaled post-GEMM features
__device__ float g_hbuf[NUM_NODES*HID];          // post agg+BN+ReLU features
__device__ float g_qkv[(size_t)NUM_NODES*QKV_DIM];
__device__ float g_obuf[NUM_NODES*HID];          // attention output (pre out-proj)
__device__ float g_wtin[HID*QKV_DIM];            // attn_in_w transposed  [K=128][384]
__device__ float g_wtout[HID*HID];               // attn_out_w transposed [128][128]
__device__ int   g_cnt[NUM_NODES];
__device__ int   g_off[NUM_NODES+1];
__device__ int   g_cur[NUM_NODES];
__device__ int   g_csrc[NUM_EDGES];
__device__ float g_dis[NUM_NODES];

// ------------------------ CSR build ------------------------
__global__ void k_zero_cnt() {
    int i = blockIdx.x*blockDim.x + threadIdx.x;
    if (i < NUM_NODES) g_cnt[i] = 0;
}

__global__ void k_degree(const int* __restrict__ dst) {
    int e = blockIdx.x*blockDim.x + threadIdx.x;
    if (e < NUM_EDGES) atomicAdd(&g_cnt[dst[e]], 1);
}

// single-block exclusive scan over 65536 ints (64 chunks x 1024, Hillis-Steele)
__global__ void k_scan() {
    __shared__ int buf[1024];
    __shared__ int carry_s;
    int tid = threadIdx.x;
    if (tid == 0) carry_s = 0;
    __syncthreads();
    for (int base = 0; base < NUM_NODES; base += 1024) {
        int v = g_cnt[base + tid];
        buf[tid] = v;
        __syncthreads();
        #pragma unroll
        for (int d = 1; d < 1024; d <<= 1) {
            int t = (tid >= d) ? buf[tid - d] : 0;
            __syncthreads();
            buf[tid] += t;
            __syncthreads();
        }
        g_off[base + tid] = carry_s + buf[tid] - v;  // exclusive
        __syncthreads();
        if (tid == 1023) carry_s += buf[1023];
        __syncthreads();
    }
    if (tid == 0) g_off[NUM_NODES] = carry_s;
}

__global__ void k_prep() {
    int i = blockIdx.x*blockDim.x + threadIdx.x;
    if (i < NUM_NODES) {
        g_dis[i] = rsqrtf((float)g_cnt[i] + 1.0f);
        g_cur[i] = g_off[i];
    }
}

__global__ void k_fill(const int* __restrict__ src, const int* __restrict__ dst) {
    int e = blockIdx.x*blockDim.x + threadIdx.x;
    if (e < NUM_EDGES) {
        int d = dst[e];
        int p = atomicAdd(&g_cur[d], 1);
        g_csrc[p] = src[e];
    }
}

// ------------------------ weight transposes ------------------------
__global__ void k_tin(const float* __restrict__ W) {   // (384,128) -> [128][384]
    int i = blockIdx.x*blockDim.x + threadIdx.x;
    if (i < QKV_DIM*HID) {
        int r = i >> 7, c = i & 127;
        g_wtin[c*QKV_DIM + r] = W[i];
    }
}
__global__ void k_tout(const float* __restrict__ W) {  // (128,128) -> [128][128]
    int i = blockIdx.x*blockDim.x + threadIdx.x;
    if (i < HID*HID) {
        int r = i >> 7, c = i & 127;
        g_wtout[c*HID + r] = W[i];
    }
}

// ------------------------ SGEMM: C[M,N-tile] = A[M,K] @ W[K,N], epilogue (+bias)*rowscale*qs
// block: 256 threads (16x16), BM=128 rows x BN=128 cols; full K resident in smem.
__global__ __launch_bounds__(256)
void k_gemm(const float* __restrict__ A, int lda,
            const float* __restrict__ W, int ldw,
            const float* __restrict__ bias,      // indexed by global col; may be null
            const float* __restrict__ rowscale,  // dis; may be null
            float qscale,                        // applied when blockIdx.y==0
            float* __restrict__ C, int ldc,
            int K, int kshift)
{
    extern __shared__ float sm[];
    float* As = sm;                  // [K][132]  (padded, transposed: As[k][row])
    float* Bs = sm + K*132;          // [K][128]
    const int tid = threadIdx.x;
    const int tx = tid & 15, ty = tid >> 4;
    const int row0 = blockIdx.x * 128;
    const int col0 = blockIdx.y * 128;

    for (int idx = tid; idx < (128 << kshift); idx += 256) {
        int r = idx >> kshift;
        int k = idx & (K - 1);
        As[k*132 + r] = A[(size_t)(row0 + r)*lda + k];
    }
    for (int idx = tid; idx < (K << 7); idx += 256) {
        int k = idx >> 7, n = idx & 127;
        Bs[k*128 + n] = W[(size_t)k*ldw + col0 + n];
    }
    __syncthreads();

    float acc[8][8];
    #pragma unroll
    for (int i = 0; i < 8; i++)
        #pragma unroll
        for (int j = 0; j < 8; j++) acc[i][j] = 0.0f;

    const int ao = ty*8, bo = tx*8;
    #pragma unroll 4
    for (int k = 0; k < K; k++) {
        float4 a0 = *(const float4*)&As[k*132 + ao];
        float4 a1 = *(const float4*)&As[k*132 + ao + 4];
        float4 b0 = *(const float4*)&Bs[k*128 + bo];
        float4 b1 = *(const float4*)&Bs[k*128 + bo + 4];
        float a[8] = {a0.x,a0.y,a0.z,a0.w,a1.x,a1.y,a1.z,a1.w};
        float b[8] = {b0.x,b0.y,b0.z,b0.w,b1.x,b1.y,b1.z,b1.w};
        #pragma unroll
        for (int i = 0; i < 8; i++)
            #pragma unroll
            for (int j = 0; j < 8; j++)
                acc[i][j] += a[i]*b[j];
    }

    const float qs = (blockIdx.y == 0) ? qscale : 1.0f;
    float bb[8];
    #pragma unroll
    for (int j = 0; j < 8; j++) bb[j] = bias ? bias[col0 + bo + j] : 0.0f;

    #pragma unroll
    for (int i = 0; i < 8; i++) {
        int r = row0 + ao + i;
        float rs = (rowscale ? rowscale[r] : 1.0f) * qs;
        float4 v0, v1;
        v0.x = (acc[i][0]+bb[0])*rs; v0.y = (acc[i][1]+bb[1])*rs;
        v0.z = (acc[i][2]+bb[2])*rs; v0.w = (acc[i][3]+bb[3])*rs;
        v1.x = (acc[i][4]+bb[4])*rs; v1.y = (acc[i][5]+bb[5])*rs;
        v1.z = (acc[i][6]+bb[6])*rs; v1.w = (acc[i][7]+bb[7])*rs;
        float* cp = &C[(size_t)r*ldc + col0 + bo];
        *(float4*)cp = v0;
        *(float4*)(cp+4) = v1;
    }
}

// ------------------------ GCN aggregate + bias + BN + ReLU ------------------------
// out[v] = relu( ((dis[v]*(sum_neigh g + g[v])) + b) * scale + shift )
__global__ __launch_bounds__(128)
void k_agg(const float* __restrict__ bias,
           const float* __restrict__ gamma, const float* __restrict__ beta,
           const float* __restrict__ mean,  const float* __restrict__ var)
{
    int warp = threadIdx.x >> 5, lane = threadIdx.x & 31;
    int node = blockIdx.x*4 + warp;
    const float4* g4 = (const float4*)g_gbuf;
    float4 acc = g4[node*32 + lane];         // self term (g = dis*h)
    int e0 = g_off[node], e1 = g_off[node+1];
    for (int e = e0; e < e1; e++) {
        int s = g_csrc[e];
        float4 t = g4[s*32 + lane];
        acc.x += t.x; acc.y += t.y; acc.z += t.z; acc.w += t.w;
    }
    float d = g_dis[node];
    int c = lane*4;
    float4 out;
    {
        float sc = gamma[c+0]*rsqrtf(var[c+0]+BN_EPS);
        out.x = fmaxf(0.0f, (d*acc.x + bias[c+0])*sc + (beta[c+0] - mean[c+0]*sc));
    }
    {
        float sc = gamma[c+1]*rsqrtf(var[c+1]+BN_EPS);
        out.y = fmaxf(0.0f, (d*acc.y + bias[c+1])*sc + (beta[c+1] - mean[c+1]*sc));
    }
    {
        float sc = gamma[c+2]*rsqrtf(var[c+2]+BN_EPS);
        out.z = fmaxf(0.0f, (d*acc.z + bias[c+2])*sc + (beta[c+2] - mean[c+2]*sc));
    }
    {
        float sc = gamma[c+3]*rsqrtf(var[c+3]+BN_EPS);
        out.w = fmaxf(0.0f, (d*acc.w + bias[c+3])*sc + (beta[c+3] - mean[c+3]*sc));
    }
    ((float4*)g_hbuf)[node*32 + lane] = out;
}

// ------------------------ attention: one block per (graph, head) ------------------------
// q pre-scaled by 1/sqrt(dh) in QKV GEMM epilogue. Online softmax, 2 q-rows/thread.
__global__ __launch_bounds__(256, 1)
void k_attn(const float* __restrict__ qkv, float* __restrict__ ob)
{
    int bid = blockIdx.x;
    int g = bid >> 2, h = bid & 3;
    extern __shared__ float sm[];
    float4* Ks = (float4*)sm;        // [512][8] float4
    float4* Vs = Ks + 512*8;
    const float* base = qkv + (size_t)g*NODES_PER_GRAPH*QKV_DIM;
    int tid = threadIdx.x;

    for (int idx = tid; idx < 512*8; idx += 256) {
        int m = idx >> 3, j = idx & 7;
        Ks[idx] = *(const float4*)(base + (size_t)m*QKV_DIM + HID   + h*32 + j*4);
        Vs[idx] = *(const float4*)(base + (size_t)m*QKV_DIM + 2*HID + h*32 + j*4);
    }
    __syncthreads();

    const int r0 = tid, r1 = tid + 256;
    float4 q0[8], q1[8], o0[8], o1[8];
    #pragma unroll
    for (int j = 0; j < 8; j++) {
        q0[j] = *(const float4*)(base + (size_t)r0*QKV_DIM + h*32 + j*4);
        q1[j] = *(const float4*)(base + (size_t)r1*QKV_DIM + h*32 + j*4);
        o0[j] = make_float4(0.f,0.f,0.f,0.f);
        o1[j] = make_float4(0.f,0.f,0.f,0.f);
    }
    float m0 = -1e30f, m1 = -1e30f, l0 = 0.f, l1 = 0.f;

    for (int mb = 0; mb < 512; mb += 8) {
        float s0[8], s1[8];
        #pragma unroll
        for (int c = 0; c < 8; c++) {
            float a0 = 0.f, a1 = 0.f;
            #pragma unroll
            for (int j = 0; j < 8; j++) {
                float4 k4 = Ks[(mb+c)*8 + j];
                a0 += q0[j].x*k4.x; a0 += q0[j].y*k4.y; a0 += q0[j].z*k4.z; a0 += q0[j].w*k4.w;
                a1 += q1[j].x*k4.x; a1 += q1[j].y*k4.y; a1 += q1[j].z*k4.z; a1 += q1[j].w*k4.w;
            }
            s0[c] = a0; s1[c] = a1;
        }
        float cm0 = s0[0], cm1 = s1[0];
        #pragma unroll
        for (int c = 1; c < 8; c++) { cm0 = fmaxf(cm0, s0[c]); cm1 = fmaxf(cm1, s1[c]); }
        float nm0 = fmaxf(m0, cm0), nm1 = fmaxf(m1, cm1);
        float al0 = __expf(m0 - nm0), al1 = __expf(m1 - nm1);
        float ps0 = 0.f, ps1 = 0.f;
        #pragma unroll
        for (int c = 0; c < 8; c++) {
            s0[c] = __expf(s0[c] - nm0); ps0 += s0[c];
            s1[c] = __expf(s1[c] - nm1); ps1 += s1[c];
        }
        l0 = l0*al0 + ps0; l1 = l1*al1 + ps1;
        m0 = nm0; m1 = nm1;
        #pragma unroll
        for (int j = 0; j < 8; j++) {
            o0[j].x *= al0; o0[j].y *= al0; o0[j].z *= al0; o0[j].w *= al0;
            o1[j].x *= al1; o1[j].y *= al1; o1[j].z *= al1; o1[j].w *= al1;
        }
        #pragma unroll
        for (int c = 0; c < 8; c++) {
            float p0 = s0[c], p1 = s1[c];
            #pragma unroll
            for (int j = 0; j < 8; j++) {
                float4 v4 = Vs[(mb+c)*8 + j];
                o0[j].x += p0*v4.x; o0[j].y += p0*v4.y; o0[j].z += p0*v4.z; o0[j].w += p0*v4.w;
                o1[j].x += p1*v4.x; o1[j].y += p1*v4.y; o1[j].z += p1*v4.z; o1[j].w += p1*v4.w;
            }
        }
    }

    float inv0 = 1.0f/l0, inv1 = 1.0f/l1;
    float* d0 = ob + (size_t)(g*NODES_PER_GRAPH + r0)*HID + h*32;
    float* d1 = ob + (size_t)(g*NODES_PER_GRAPH + r1)*HID + h*32;
    #pragma unroll
    for (int j = 0; j < 8; j++) {
        float4 w;
        w.x = o0[j].x*inv0; w.y = o0[j].y*inv0; w.z = o0[j].z*inv0; w.w = o0[j].w*inv0;
        *(float4*)(d0 + j*4) = w;
        w.x = o1[j].x*inv1; w.y = o1[j].y*inv1; w.z = o1[j].z*inv1; w.w = o1[j].w*inv1;
        *(float4*)(d1 + j*4) = w;
    }
}

// ------------------------ global mean pool (contiguous equal-size graphs) ------------------------
__global__ void k_pool(const float* __restrict__ fin, float* __restrict__ emb)
{
    int g = blockIdx.x, c = threadIdx.x;
    const float* p = fin + (size_t)g*NODES_PER_GRAPH*HID + c;
    float s = 0.f;
    for (int r = 0; r < NODES_PER_GRAPH; r++) s += p[(size_t)r*HID];
    emb[g*HID + c] = s * (1.0f/NODES_PER_GRAPH);
}

// ------------------------ launch ------------------------
extern "C" void kernel_launch(void* const* d_in, const int* in_sizes, int n_in,
                              void* d_out, int out_size)
{
    const float* x      = (const float*)d_in[0];
    const float* W0     = (const float*)d_in[1];
    const float* b0     = (const float*)d_in[2];
    const float* Wh     = (const float*)d_in[3];
    const float* bh     = (const float*)d_in[4];
    const float* bn_g   = (const float*)d_in[5];
    const float* bn_b   = (const float*)d_in[6];
    const float* bn_m   = (const float*)d_in[7];
    const float* bn_v   = (const float*)d_in[8];
    const float* ain_w  = (const float*)d_in[9];
    const float* ain_b  = (const float*)d_in[10];
    const float* aout_w = (const float*)d_in[11];
    const float* aout_b = (const float*)d_in[12];
    const int*   eidx   = (const int*)d_in[13];
    const int* esrc = eidx;
    const int* edst = eidx + NUM_EDGES;

    float* outF = (float*)d_out;
    float* outE = outF + (size_t)NUM_NODES*HID;

    void* p;
    cudaGetSymbolAddress(&p, g_gbuf);  float* gbuf  = (float*)p;
    cudaGetSymbolAddress(&p, g_hbuf);  float* hbuf  = (float*)p;
    cudaGetSymbolAddress(&p, g_qkv);   float* qkv   = (float*)p;
    cudaGetSymbolAddress(&p, g_obuf);  float* obuf  = (float*)p;
    cudaGetSymbolAddress(&p, g_wtin);  float* wtin  = (float*)p;
    cudaGetSymbolAddress(&p, g_wtout); float* wtout = (float*)p;
    cudaGetSymbolAddress(&p, g_dis);   float* dis   = (float*)p;

    const int SMEM64  = 64*132*4  + 64*128*4;   // 66560
    const int SMEM128 = 128*132*4 + 128*128*4;  // 133120
    const int SMEM_ATTN = 512*32*2*4;           // 131072
    cudaFuncSetAttribute(k_gemm, cudaFuncAttributeMaxDynamicSharedMemorySize, SMEM128);
    cudaFuncSetAttribute(k_attn, cudaFuncAttributeMaxDynamicSharedMemorySize, SMEM_ATTN);

    // CSR build (per-launch, deterministic work)
    k_zero_cnt<<<64, 1024>>>();
    k_degree<<<NUM_EDGES/256, 256>>>(edst);
    k_scan<<<1, 1024>>>();
    k_prep<<<64, 1024>>>();
    k_fill<<<NUM_EDGES/256, 256>>>(esrc, edst);
    k_tin <<<(QKV_DIM*HID + 255)/256, 256>>>(ain_w);
    k_tout<<<(HID*HID + 255)/256, 256>>>(aout_w);

    const int MB = NUM_NODES/128;  // 512 row-blocks

    // layer 0: g = dis * (x @ W0)
    k_gemm<<<dim3(MB,1), 256, SMEM64>>>(x, IN_DIM, W0, HID, nullptr, dis, 1.0f,
                                        gbuf, HID, IN_DIM, 6);
    k_agg<<<NUM_NODES/4, 128>>>(b0, bn_g, bn_b, bn_m, bn_v);

    // layers 1..3
    for (int l = 0; l < 3; l++) {
        k_gemm<<<dim3(MB,1), 256, SMEM128>>>(hbuf, HID, Wh + (size_t)l*HID*HID, HID,
                                             nullptr, dis, 1.0f, gbuf, HID, HID, 7);
        k_agg<<<NUM_NODES/4, 128>>>(bh + l*HID, bn_g + (l+1)*HID, bn_b + (l+1)*HID,
                                    bn_m + (l+1)*HID, bn_v + (l+1)*HID);
    }

    // QKV projection (q block pre-scaled by 1/sqrt(32))
    k_gemm<<<dim3(MB,3), 256, SMEM128>>>(hbuf, HID, wtin, QKV_DIM, ain_b,
                                         nullptr, 0.17677669529663687f,
                                         qkv, QKV_DIM, HID, 7);

    // attention: one block per (graph, head)
    k_attn<<<NUM_GRAPHS*4, 256, SMEM_ATTN>>>(qkv, obuf);

    // output projection -> final
    k_gemm<<<dim3(MB,1), 256, SMEM128>>>(obuf, HID, wtout, HID, aout_b,
                                         nullptr, 1.0f, outF, HID, HID, 7);

    // mean pool -> graph_emb
    k_pool<<<NUM_GRAPHS, HID>>>(outF, outE);
}

// round 7
// speedup vs baseline: 1.3539x; 1.3539x over previous
#include <cuda_runtime.h>
#include <cuda_bf16.h>
#include <math.h>
#include <stddef.h>
#include <stdint.h>

#define NUM_GRAPHS 128
#define NODES_PER_GRAPH 512
#define NUM_NODES (NUM_GRAPHS*NODES_PER_GRAPH)   // 65536
#define NUM_EDGES (NUM_NODES*16)                 // 1048576
#define IN_DIM 64
#define HID 128
#define QKV_DIM 384
#define BN_EPS 1e-5f

// ------------------------ scratch (device globals: no allocation) ------------------------
__device__ float g_gbuf[NUM_NODES*HID];
__device__ float g_hbuf[NUM_NODES*HID];
__device__ float g_qkv[(size_t)NUM_NODES*QKV_DIM];
__device__ float g_obuf[NUM_NODES*HID];
__device__ int   g_cnt[NUM_NODES];
__device__ int   g_off[NUM_NODES+1];
__device__ int   g_cur[NUM_NODES];
__device__ int   g_csrc[NUM_EDGES];
__device__ float g_dis[NUM_NODES];
// pre-split bf16 hi/lo weight planes, padded stride (K+8), [n][k] layout per 128-col block
// L0: 2*128*72 = 18432 elems; L1..3 / OUT: 2*128*136 = 34816 each; QKV: 3*34816
__device__ __nv_bfloat16 g_bw[262144];
#define OFF_L0   0
#define OFF_L(l) (18432 + (l)*34816)
#define OFF_QKV  (18432 + 3*34816)
#define OFF_OUT  (OFF_QKV + 3*34816)

// ------------------------ helpers ------------------------
__device__ __forceinline__ uint32_t smem_u32(const void* p){
    uint32_t a;
    asm("{ .reg .u64 t; cvta.to.shared.u64 t, %1; cvt.u32.u64 %0, t; }" : "=r"(a) : "l"(p));
    return a;
}
__device__ __forceinline__ void ldsm4(uint32_t* r, uint32_t addr){
    asm volatile("ldmatrix.sync.aligned.m8n8.x4.shared.b16 {%0,%1,%2,%3}, [%4];"
        : "=r"(r[0]),"=r"(r[1]),"=r"(r[2]),"=r"(r[3]) : "r"(addr));
}
__device__ __forceinline__ void mma16816(float* c, const uint32_t* a, uint32_t b0, uint32_t b1){
    asm volatile("mma.sync.aligned.m16n8k16.row.col.f32.bf16.bf16.f32 "
        "{%0,%1,%2,%3}, {%4,%5,%6,%7}, {%8,%9}, {%0,%1,%2,%3};"
        : "+f"(c[0]),"+f"(c[1]),"+f"(c[2]),"+f"(c[3])
        : "r"(a[0]),"r"(a[1]),"r"(a[2]),"r"(a[3]), "r"(b0),"r"(b1));
}

// ------------------------ CSR build ------------------------
__global__ void k_zero_cnt() {
    int i = blockIdx.x*blockDim.x + threadIdx.x;
    if (i < NUM_NODES) g_cnt[i] = 0;
}
__global__ void k_degree(const int* __restrict__ dst) {
    int e = blockIdx.x*blockDim.x + threadIdx.x;
    if (e < NUM_EDGES) atomicAdd(&g_cnt[dst[e]], 1);
}
__global__ void k_scan() {
    __shared__ int buf[1024];
    __shared__ int carry_s;
    int tid = threadIdx.x;
    if (tid == 0) carry_s = 0;
    __syncthreads();
    for (int base = 0; base < NUM_NODES; base += 1024) {
        int v = g_cnt[base + tid];
        buf[tid] = v;
        __syncthreads();
        #pragma unroll
        for (int d = 1; d < 1024; d <<= 1) {
            int t = (tid >= d) ? buf[tid - d] : 0;
            __syncthreads();
            buf[tid] += t;
            __syncthreads();
        }
        g_off[base + tid] = carry_s + buf[tid] - v;
        __syncthreads();
        if (tid == 1023) carry_s += buf[1023];
        __syncthreads();
    }
    if (tid == 0) g_off[NUM_NODES] = carry_s;
}
__global__ void k_prep() {
    int i = blockIdx.x*blockDim.x + threadIdx.x;
    if (i < NUM_NODES) {
        g_dis[i] = rsqrtf((float)g_cnt[i] + 1.0f);
        g_cur[i] = g_off[i];
    }
}
__global__ void k_fill(const int* __restrict__ src, const int* __restrict__ dst) {
    int e = blockIdx.x*blockDim.x + threadIdx.x;
    if (e < NUM_EDGES) {
        int d = dst[e];
        int p = atomicAdd(&g_cur[d], 1);
        g_csrc[p] = src[e];
    }
}

// ------------------------ weight prep: B[n][k] bf16 hi/lo planes, stride K+8 ------------------------
__global__ void k_prepB(const float* __restrict__ W, int Nsrc, int K, int transpose,
                        __nv_bfloat16* __restrict__ dst, int total)
{
    int idx = blockIdx.x*blockDim.x + threadIdx.x;
    if (idx >= total) return;
    int n = idx / K, k = idx - n*K;
    float x = transpose ? W[(size_t)k*Nsrc + n] : W[(size_t)n*K + k];
    int stride = K + 8;
    int planeE = 128*stride;
    int cb = n >> 7, nr = n & 127;
    __nv_bfloat16 hi = __float2bfloat16_rn(x);
    __nv_bfloat16 lo = __float2bfloat16_rn(x - __bfloat162float(hi));
    __nv_bfloat16* d = dst + (size_t)cb*2*planeE;
    d[nr*stride + k] = hi;
    d[planeE + nr*stride + k] = lo;
}

// ------------------------ HMMA GEMM: C[128,128] = A[128,K] @ B^T, bf16 hi/lo split, fp32 accum
// 256 threads = 8 warps, warp tile 32x64 (4 warps along M, 2 along N).
// smem planes: [Ahi][Alo][Bhi][Blo], each 128 x (K+8) bf16.
__global__ __launch_bounds__(256)
void k_gemm_mma(const float* __restrict__ A, int lda, int kshift,
                const __nv_bfloat16* __restrict__ Bplanes,
                const float* __restrict__ bias, const float* __restrict__ rowscale,
                float qscale, float* __restrict__ C, int ldc)
{
    extern __shared__ unsigned char smraw[];
    const int K = 1 << kshift;
    const int stride = K + 8;
    const int planeE = 128*stride;
    __nv_bfloat16* Ahi = (__nv_bfloat16*)smraw;
    __nv_bfloat16* Alo = Ahi + planeE;
    __nv_bfloat16* Bhi = Alo + planeE;
    const int tid = threadIdx.x;
    const int row0 = blockIdx.x*128, col0 = blockIdx.y*128;

    // B: linear copy of pre-built hi+lo planes for this column block
    {
        const uint4* src = (const uint4*)(Bplanes + (size_t)blockIdx.y*2*planeE);
        uint4* dst = (uint4*)Bhi;
        const int n16 = 2*planeE/8;       // uint4 = 8 bf16
        for (int i = tid; i < n16; i += 256) dst[i] = src[i];
    }
    // A: fp32 -> bf16 hi/lo split into smem
    {
        const int k4 = K >> 2;
        const int tot = 128*k4;
        for (int idx = tid; idx < tot; idx += 256) {
            int r = idx >> (kshift-2);
            int c = (idx & (k4-1)) << 2;
            float4 v = *(const float4*)&A[(size_t)(row0+r)*lda + c];
            unsigned short h0 = __bfloat16_as_ushort(__float2bfloat16_rn(v.x));
            unsigned short h1 = __bfloat16_as_ushort(__float2bfloat16_rn(v.y));
            unsigned short h2 = __bfloat16_as_ushort(__float2bfloat16_rn(v.z));
            unsigned short h3 = __bfloat16_as_ushort(__float2bfloat16_rn(v.w));
            unsigned short l0 = __bfloat16_as_ushort(__float2bfloat16_rn(v.x - __bfloat162float(__ushort_as_bfloat16(h0))));
            unsigned short l1 = __bfloat16_as_ushort(__float2bfloat16_rn(v.y - __bfloat162float(__ushort_as_bfloat16(h1))));
            unsigned short l2 = __bfloat16_as_ushort(__float2bfloat16_rn(v.z - __bfloat162float(__ushort_as_bfloat16(h2))));
            unsigned short l3 = __bfloat16_as_ushort(__float2bfloat16_rn(v.w - __bfloat162float(__ushort_as_bfloat16(h3))));
            uint2 hv, lv;
            hv.x = (uint32_t)h0 | ((uint32_t)h1 << 16);
            hv.y = (uint32_t)h2 | ((uint32_t)h3 << 16);
            lv.x = (uint32_t)l0 | ((uint32_t)l1 << 16);
            lv.y = (uint32_t)l2 | ((uint32_t)l3 << 16);
            *(uint2*)&Ahi[r*stride + c] = hv;
            *(uint2*)&Alo[r*stride + c] = lv;
        }
    }
    __syncthreads();

    const int lane = tid & 31, w = tid >> 5;
    const int wm = w & 3, wn = w >> 2;
    const uint32_t sbase = smem_u32(smraw);
    const uint32_t pA_hi = sbase;
    const uint32_t pA_lo = sbase + (uint32_t)planeE*2;
    const uint32_t pB_hi = sbase + (uint32_t)planeE*4;
    const uint32_t pB_lo = sbase + (uint32_t)planeE*6;

    float acc[2][8][4];
    #pragma unroll
    for (int i = 0; i < 2; i++)
        #pragma unroll
        for (int j = 0; j < 8; j++)
            #pragma unroll
            for (int q = 0; q < 4; q++) acc[i][j][q] = 0.0f;

    // ldmatrix lane address components (bf16 element offsets)
    const int a_row = lane & 15;
    const int a_kof = (lane >> 4) << 3;
    const int b_row = (lane & 7) + ((lane >> 4) << 3);
    const int b_kof = ((lane >> 3) & 1) << 3;

    const uint32_t aA[3] = {pA_hi, pA_hi, pA_lo};
    const uint32_t aB[3] = {pB_hi, pB_lo, pB_hi};

    #pragma unroll
    for (int cmb = 0; cmb < 3; cmb++) {
        const uint32_t Abase = aA[cmb] + (uint32_t)((wm*32 + a_row)*stride + a_kof)*2u;
        const uint32_t Bbase = aB[cmb] + (uint32_t)((wn*64 + b_row)*stride + b_kof)*2u;
        for (int ks = 0; ks < K; ks += 16) {
            uint32_t af[2][4];
            #pragma unroll
            for (int mt = 0; mt < 2; mt++)
                ldsm4(af[mt], Abase + (uint32_t)(mt*16*stride + ks)*2u);
            #pragma unroll
            for (int np = 0; np < 4; np++) {
                uint32_t bf[4];
                ldsm4(bf, Bbase + (uint32_t)(np*16*stride + ks)*2u);
                #pragma unroll
                for (int mt = 0; mt < 2; mt++) {
                    mma16816(acc[mt][np*2+0], af[mt], bf[0], bf[1]);
                    mma16816(acc[mt][np*2+1], af[mt], bf[2], bf[3]);
                }
            }
        }
    }

    // epilogue: (acc + bias[col]) * rowscale[row] * (qscale if colblock 0)
    const float qs = (blockIdx.y == 0) ? qscale : 1.0f;
    const int rbase = row0 + wm*32 + (lane >> 2);
    const int cbase = col0 + wn*64 + (lane & 3)*2;
    float bb[8][2];
    #pragma unroll
    for (int nt = 0; nt < 8; nt++) {
        int cc = cbase + nt*8;
        bb[nt][0] = bias ? bias[cc]   : 0.0f;
        bb[nt][1] = bias ? bias[cc+1] : 0.0f;
    }
    #pragma unroll
    for (int mt = 0; mt < 2; mt++) {
        #pragma unroll
        for (int half = 0; half < 2; half++) {
            int r = rbase + mt*16 + half*8;
            float rs = (rowscale ? rowscale[r] : 1.0f) * qs;
            float* cp = C + (size_t)r*ldc;
            #pragma unroll
            for (int nt = 0; nt < 8; nt++) {
                int cc = cbase + nt*8;
                float2 v;
                v.x = (acc[mt][nt][half*2+0] + bb[nt][0])*rs;
                v.y = (acc[mt][nt][half*2+1] + bb[nt][1])*rs;
                *(float2*)&cp[cc] = v;
            }
        }
    }
}

// ------------------------ GCN aggregate + bias + BN + ReLU ------------------------
__global__ __launch_bounds__(128)
void k_agg(const float* __restrict__ bias,
           const float* __restrict__ gamma, const float* __restrict__ beta,
           const float* __restrict__ mean,  const float* __restrict__ var)
{
    int warp = threadIdx.x >> 5, lane = threadIdx.x & 31;
    int node = blockIdx.x*4 + warp;
    const float4* g4 = (const float4*)g_gbuf;
    float4 acc = g4[node*32 + lane];
    int e0 = g_off[node], e1 = g_off[node+1];
    for (int e = e0; e < e1; e++) {
        int s = g_csrc[e];
        float4 t = g4[s*32 + lane];
        acc.x += t.x; acc.y += t.y; acc.z += t.z; acc.w += t.w;
    }
    float d = g_dis[node];
    int c = lane*4;
    float4 out;
    {
        float sc = gamma[c+0]*rsqrtf(var[c+0]+BN_EPS);
        out.x = fmaxf(0.0f, (d*acc.x + bias[c+0])*sc + (beta[c+0] - mean[c+0]*sc));
    }
    {
        float sc = gamma[c+1]*rsqrtf(var[c+1]+BN_EPS);
        out.y = fmaxf(0.0f, (d*acc.y + bias[c+1])*sc + (beta[c+1] - mean[c+1]*sc));
    }
    {
        float sc = gamma[c+2]*rsqrtf(var[c+2]+BN_EPS);
        out.z = fmaxf(0.0f, (d*acc.z + bias[c+2])*sc + (beta[c+2] - mean[c+2]*sc));
    }
    {
        float sc = gamma[c+3]*rsqrtf(var[c+3]+BN_EPS);
        out.w = fmaxf(0.0f, (d*acc.w + bias[c+3])*sc + (beta[c+3] - mean[c+3]*sc));
    }
    ((float4*)g_hbuf)[node*32 + lane] = out;
}

// ------------------------ attention (fp32, online softmax) ------------------------
__global__ __launch_bounds__(256, 1)
void k_attn(const float* __restrict__ qkv, float* __restrict__ ob)
{
    int bid = blockIdx.x;
    int g = bid >> 2, h = bid & 3;
    extern __shared__ float smf[];
    float4* Ks = (float4*)smf;
    float4* Vs = Ks + 512*8;
    const float* base = qkv + (size_t)g*NODES_PER_GRAPH*QKV_DIM;
    int tid = threadIdx.x;

    for (int idx = tid; idx < 512*8; idx += 256) {
        int m = idx >> 3, j = idx & 7;
        Ks[idx] = *(const float4*)(base + (size_t)m*QKV_DIM + HID   + h*32 + j*4);
        Vs[idx] = *(const float4*)(base + (size_t)m*QKV_DIM + 2*HID + h*32 + j*4);
    }
    __syncthreads();

    const int r0 = tid, r1 = tid + 256;
    float4 q0[8], q1[8], o0[8], o1[8];
    #pragma unroll
    for (int j = 0; j < 8; j++) {
        q0[j] = *(const float4*)(base + (size_t)r0*QKV_DIM + h*32 + j*4);
        q1[j] = *(const float4*)(base + (size_t)r1*QKV_DIM + h*32 + j*4);
        o0[j] = make_float4(0.f,0.f,0.f,0.f);
        o1[j] = make_float4(0.f,0.f,0.f,0.f);
    }
    float m0 = -1e30f, m1 = -1e30f, l0 = 0.f, l1 = 0.f;

    for (int mb = 0; mb < 512; mb += 8) {
        float s0[8], s1[8];
        #pragma unroll
        for (int c = 0; c < 8; c++) {
            float a0 = 0.f, a1 = 0.f;
            #pragma unroll
            for (int j = 0; j < 8; j++) {
                float4 k4 = Ks[(mb+c)*8 + j];
                a0 += q0[j].x*k4.x; a0 += q0[j].y*k4.y; a0 += q0[j].z*k4.z; a0 += q0[j].w*k4.w;
                a1 += q1[j].x*k4.x; a1 += q1[j].y*k4.y; a1 += q1[j].z*k4.z; a1 += q1[j].w*k4.w;
            }
            s0[c] = a0; s1[c] = a1;
        }
        float cm0 = s0[0], cm1 = s1[0];
        #pragma unroll
        for (int c = 1; c < 8; c++) { cm0 = fmaxf(cm0, s0[c]); cm1 = fmaxf(cm1, s1[c]); }
        float nm0 = fmaxf(m0, cm0), nm1 = fmaxf(m1, cm1);
        float al0 = __expf(m0 - nm0), al1 = __expf(m1 - nm1);
        float ps0 = 0.f, ps1 = 0.f;
        #pragma unroll
        for (int c = 0; c < 8; c++) {
            s0[c] = __expf(s0[c] - nm0); ps0 += s0[c];
            s1[c] = __expf(s1[c] - nm1); ps1 += s1[c];
        }
        l0 = l0*al0 + ps0; l1 = l1*al1 + ps1;
        m0 = nm0; m1 = nm1;
        #pragma unroll
        for (int j = 0; j < 8; j++) {
            o0[j].x *= al0; o0[j].y *= al0; o0[j].z *= al0; o0[j].w *= al0;
            o1[j].x *= al1; o1[j].y *= al1; o1[j].z *= al1; o1[j].w *= al1;
        }
        #pragma unroll
        for (int c = 0; c < 8; c++) {
            float p0 = s0[c], p1 = s1[c];
            #pragma unroll
            for (int j = 0; j < 8; j++) {
                float4 v4 = Vs[(mb+c)*8 + j];
                o0[j].x += p0*v4.x; o0[j].y += p0*v4.y; o0[j].z += p0*v4.z; o0[j].w += p0*v4.w;
                o1[j].x += p1*v4.x; o1[j].y += p1*v4.y; o1[j].z += p1*v4.z; o1[j].w += p1*v4.w;
            }
        }
    }

    float inv0 = 1.0f/l0, inv1 = 1.0f/l1;
    float* d0 = ob + (size_t)(g*NODES_PER_GRAPH + r0)*HID + h*32;
    float* d1 = ob + (size_t)(g*NODES_PER_GRAPH + r1)*HID + h*32;
    #pragma unroll
    for (int j = 0; j < 8; j++) {
        float4 w;
        w.x = o0[j].x*inv0; w.y = o0[j].y*inv0; w.z = o0[j].z*inv0; w.w = o0[j].w*inv0;
        *(float4*)(d0 + j*4) = w;
        w.x = o1[j].x*inv1; w.y = o1[j].y*inv1; w.z = o1[j].z*inv1; w.w = o1[j].w*inv1;
        *(float4*)(d1 + j*4) = w;
    }
}

// ------------------------ global mean pool ------------------------
__global__ void k_pool(const float* __restrict__ fin, float* __restrict__ emb)
{
    int g = blockIdx.x, c = threadIdx.x;
    const float* p = fin + (size_t)g*NODES_PER_GRAPH*HID + c;
    float s = 0.f;
    for (int r = 0; r < NODES_PER_GRAPH; r++) s += p[(size_t)r*HID];
    emb[g*HID + c] = s * (1.0f/NODES_PER_GRAPH);
}

// ------------------------ launch ------------------------
extern "C" void kernel_launch(void* const* d_in, const int* in_sizes, int n_in,
                              void* d_out, int out_size)
{
    const float* x      = (const float*)d_in[0];
    const float* W0     = (const float*)d_in[1];
    const float* b0     = (const float*)d_in[2];
    const float* Wh     = (const float*)d_in[3];
    const float* bh     = (const float*)d_in[4];
    const float* bn_g   = (const float*)d_in[5];
    const float* bn_b   = (const float*)d_in[6];
    const float* bn_m   = (const float*)d_in[7];
    const float* bn_v   = (const float*)d_in[8];
    const float* ain_w  = (const float*)d_in[9];
    const float* ain_b  = (const float*)d_in[10];
    const float* aout_w = (const float*)d_in[11];
    const float* aout_b = (const float*)d_in[12];
    const int*   eidx   = (const int*)d_in[13];
    const int* esrc = eidx;
    const int* edst = eidx + NUM_EDGES;

    float* outF = (float*)d_out;
    float* outE = outF + (size_t)NUM_NODES*HID;

    void* p;
    cudaGetSymbolAddress(&p, g_gbuf);  float* gbuf  = (float*)p;
    cudaGetSymbolAddress(&p, g_hbuf);  float* hbuf  = (float*)p;
    cudaGetSymbolAddress(&p, g_qkv);   float* qkv   = (float*)p;
    cudaGetSymbolAddress(&p, g_obuf);  float* obuf  = (float*)p;
    cudaGetSymbolAddress(&p, g_dis);   float* dis   = (float*)p;
    cudaGetSymbolAddress(&p, g_bw);    __nv_bfloat16* bw = (__nv_bfloat16*)p;

    const int SM_K64  = 4*128*72*2;    // 73728
    const int SM_K128 = 4*128*136*2;   // 139264
    const int SMEM_ATTN = 512*32*2*4;  // 131072
    cudaFuncSetAttribute(k_gemm_mma, cudaFuncAttributeMaxDynamicSharedMemorySize, SM_K128);
    cudaFuncSetAttribute(k_attn, cudaFuncAttributeMaxDynamicSharedMemorySize, SMEM_ATTN);

    // CSR build
    k_zero_cnt<<<64, 1024>>>();
    k_degree<<<NUM_EDGES/256, 256>>>(edst);
    k_scan<<<1, 1024>>>();
    k_prep<<<64, 1024>>>();
    k_fill<<<NUM_EDGES/256, 256>>>(esrc, edst);

    // weight prep: bf16 hi/lo planes
    k_prepB<<<(8192+255)/256, 256>>>(W0, 128, 64, 1, bw + OFF_L0, 8192);
    for (int l = 0; l < 3; l++)
        k_prepB<<<(16384+255)/256, 256>>>(Wh + (size_t)l*HID*HID, 128, 128, 1, bw + OFF_L(l), 16384);
    k_prepB<<<(49152+255)/256, 256>>>(ain_w, 0, 128, 0, bw + OFF_QKV, 49152);
    k_prepB<<<(16384+255)/256, 256>>>(aout_w, 0, 128, 0, bw + OFF_OUT, 16384);

    const int MB = NUM_NODES/128;  // 512

    // layer 0: g = dis * (x @ W0)
    k_gemm_mma<<<dim3(MB,1), 256, SM_K64>>>(x, IN_DIM, 6, bw + OFF_L0,
                                            nullptr, dis, 1.0f, gbuf, HID);
    k_agg<<<NUM_NODES/4, 128>>>(b0, bn_g, bn_b, bn_m, bn_v);

    // layers 1..3
    for (int l = 0; l < 3; l++) {
        k_gemm_mma<<<dim3(MB,1), 256, SM_K128>>>(hbuf, HID, 7, bw + OFF_L(l),
                                                 nullptr, dis, 1.0f, gbuf, HID);
        k_agg<<<NUM_NODES/4, 128>>>(bh + l*HID, bn_g + (l+1)*HID, bn_b + (l+1)*HID,
                                    bn_m + (l+1)*HID, bn_v + (l+1)*HID);
    }

    // QKV projection (q colblock pre-scaled by 1/sqrt(32))
    k_gemm_mma<<<dim3(MB,3), 256, SM_K128>>>(hbuf, HID, 7, bw + OFF_QKV,
                                             ain_b, nullptr, 0.17677669529663687f,
                                             qkv, QKV_DIM);

    // attention
    k_attn<<<NUM_GRAPHS*4, 256, SMEM_ATTN>>>(qkv, obuf);

    // output projection -> final
    k_gemm_mma<<<dim3(MB,1), 256, SM_K128>>>(obuf, HID, 7, bw + OFF_OUT,
                                             aout_b, nullptr, 1.0f, outF, HID);

    // mean pool -> graph_emb
    k_pool<<<NUM_GRAPHS, HID>>>(outF, outE);
}